// round 8
// baseline (speedup 1.0000x reference)
#include <cuda_runtime.h>
#include <math.h>

#define Bb 16
#define Tt 2048
#define Ii 512
#define Hh 512
#define RR 2048   // 4*H, permuted row order r = 4*j + g
#define NG 4      // independent groups (each owns 4 batches)
#define GC 32     // CTAs per group
#define GB 4      // batches per group
#define WKS 68    // w_s k-row stride in floats (512*68*4B = 136KB)

// ---------------- persistent device scratch (no runtime allocation) ----------
__device__ float d_WiP[RR * Ii];                 // 4 MB  permuted Wi
__device__ float d_WhT[(size_t)Hh * RR];         // 4 MB  Wh transposed [k][rnew]
__device__ float d_bsum[RR];                     // bi+bh, permuted
__device__ float d_XG[(size_t)Tt * RR * Bb];     // 268 MB, [t][g][r][b4]
__device__ uint2 d_HX[2][NG * Hh * GB];          // tagged h words (h_bits, tag)

// ---------------- f32x2 helpers ----------------------------------------------
__device__ __forceinline__ unsigned long long ffma2(unsigned long long a,
                                                    unsigned long long b,
                                                    unsigned long long c) {
    unsigned long long d;
    asm("fma.rn.f32x2 %0, %1, %2, %3;" : "=l"(d) : "l"(a), "l"(b), "l"(c));
    return d;
}
__device__ __forceinline__ unsigned long long add2(unsigned long long a,
                                                   unsigned long long b) {
    unsigned long long d;
    asm("add.rn.f32x2 %0, %1, %2;" : "=l"(d) : "l"(a), "l"(b));
    return d;
}
__device__ __forceinline__ unsigned long long packdup(float x) {
    unsigned long long r;
    asm("mov.b64 %0, {%1, %1};" : "=l"(r) : "f"(x));
    return r;
}
__device__ __forceinline__ float2 unpk(unsigned long long v) {
    float2 r;
    asm("mov.b64 {%0, %1}, %2;" : "=f"(r.x), "=f"(r.y) : "l"(v));
    return r;
}
__device__ __forceinline__ unsigned long long shflx64(unsigned long long v, int m) {
    unsigned lo, hi;
    asm("mov.b64 {%0, %1}, %2;" : "=r"(lo), "=r"(hi) : "l"(v));
    lo = __shfl_xor_sync(0xFFFFFFFFu, lo, m);
    hi = __shfl_xor_sync(0xFFFFFFFFu, hi, m);
    unsigned long long r;
    asm("mov.b64 %0, {%1, %2};" : "=l"(r) : "r"(lo), "r"(hi));
    return r;
}

// fresh L2 read of 16B (2 tagged words), never hoisted
__device__ __forceinline__ uint4 ldcg4(const uint4* p) {
    uint4 v;
    asm volatile("ld.global.cg.v4.u32 {%0,%1,%2,%3}, [%4];"
                 : "=r"(v.x), "=r"(v.y), "=r"(v.z), "=r"(v.w)
                 : "l"(p) : "memory");
    return v;
}
// publish one tagged word (data+tag atomic in a single 8B store)
__device__ __forceinline__ void st_word(uint2* p, unsigned hbits, unsigned tag) {
    asm volatile("st.global.cg.v2.u32 [%0], {%1, %2};"
                 :: "l"(p), "r"(hbits), "r"(tag) : "memory");
}

__device__ __forceinline__ float sigmoidf_(float x) {
    return 1.f / (1.f + __expf(-x));
}
__device__ __forceinline__ float tanhf_(float x) {
    float e = __expf(2.f * x);
    return (e - 1.f) / (e + 1.f);
}

// ---------------- phase 0a: permute Wi, transpose Wh, fuse biases ------------
__global__ void permute_kernel(const float* __restrict__ Wi,
                               const float* __restrict__ Wh,
                               const float* __restrict__ bi,
                               const float* __restrict__ bh) {
    int rnew = blockIdx.x;            // 0..2047
    int j = rnew >> 2, g = rnew & 3;
    int rold = g * Hh + j;
    const float4* wi4 = (const float4*)(Wi + (size_t)rold * Ii);
    float4* wiP4 = (float4*)(d_WiP + (size_t)rnew * Ii);
    for (int k = threadIdx.x; k < Ii / 4; k += blockDim.x) wiP4[k] = wi4[k];
    // Wh transpose: d_WhT[k][rnew]
    const float* whr = Wh + (size_t)rold * Hh;
    for (int k = threadIdx.x; k < Hh; k += blockDim.x)
        d_WhT[(size_t)k * RR + rnew] = whr[k];
    if (threadIdx.x == 0) d_bsum[rnew] = bi[rold] + bh[rold];
}

// ---------------- phase 0b: init tagged h words ------------------------------
__global__ void init_kernel(const float* __restrict__ h0) {
    int idx = blockIdx.x * blockDim.x + threadIdx.x;   // 0..8191
    if (idx < NG * Hh * GB) {
        int g = idx >> 11;
        int k = (idx & 2047) >> 2;
        int b = idx & 3;
        float h = h0[(size_t)(g * GB + b) * Hh + k];
        d_HX[0][idx] = make_uint2(__float_as_uint(h), 0u);       // tag 0 = h(0)
        d_HX[1][idx] = make_uint2(0u, 0xFFFFFFFFu);              // never matches
    }
}

// ---------------- phase 1: xg[t][g][r][b4] = WiP @ x^T + bsum ----------------
#define BM 128
#define BN 128
#define BK 16
#define LDA 132

__global__ __launch_bounds__(256, 2) void xgemm_kernel(const float* __restrict__ x) {
    __shared__ float As[BK * LDA];
    __shared__ float Bs[BK * LDA];
    const int tid = threadIdx.x;
    const int m0 = blockIdx.y * BM;
    const int n0 = blockIdx.x * BN;
    const int tx = tid & 15, ty = tid >> 4;

    unsigned long long acc[8][4];
#pragma unroll
    for (int i = 0; i < 8; i++)
#pragma unroll
        for (int j = 0; j < 4; j++) acc[i][j] = 0ull;

    for (int k0 = 0; k0 < Ii; k0 += BK) {
#pragma unroll
        for (int q = 0; q < 2; q++) {
            int slot = tid + q * 256;
            int row = slot >> 2;
            int kq4 = slot & 3;
            float4 v = *(const float4*)&d_WiP[(size_t)(m0 + row) * Ii + k0 + kq4 * 4];
            As[(kq4 * 4 + 0) * LDA + row] = v.x;
            As[(kq4 * 4 + 1) * LDA + row] = v.y;
            As[(kq4 * 4 + 2) * LDA + row] = v.z;
            As[(kq4 * 4 + 3) * LDA + row] = v.w;
        }
#pragma unroll
        for (int q = 0; q < 2; q++) {
            int slot = tid + q * 256;
            int nn = slot >> 2;
            int kq4 = slot & 3;
            int n = n0 + nn;
            int t = n >> 4, b = n & 15;
            float4 v = *(const float4*)&x[((size_t)b * Tt + t) * Ii + k0 + kq4 * 4];
            Bs[(kq4 * 4 + 0) * LDA + nn] = v.x;
            Bs[(kq4 * 4 + 1) * LDA + nn] = v.y;
            Bs[(kq4 * 4 + 2) * LDA + nn] = v.z;
            Bs[(kq4 * 4 + 3) * LDA + nn] = v.w;
        }
        __syncthreads();
#pragma unroll
        for (int kk = 0; kk < BK; kk++) {
            float a[8];
            *(float4*)&a[0] = *(const float4*)&As[kk * LDA + ty * 8];
            *(float4*)&a[4] = *(const float4*)&As[kk * LDA + ty * 8 + 4];
            ulonglong2 b01 = *(const ulonglong2*)&Bs[kk * LDA + tx * 8];
            ulonglong2 b23 = *(const ulonglong2*)&Bs[kk * LDA + tx * 8 + 4];
#pragma unroll
            for (int i = 0; i < 8; i++) {
                unsigned long long as = packdup(a[i]);
                acc[i][0] = ffma2(as, b01.x, acc[i][0]);
                acc[i][1] = ffma2(as, b01.y, acc[i][1]);
                acc[i][2] = ffma2(as, b23.x, acc[i][2]);
                acc[i][3] = ffma2(as, b23.y, acc[i][3]);
            }
        }
        __syncthreads();
    }
#pragma unroll
    for (int mm = 0; mm < 8; mm++) {
        int r = m0 + ty * 8 + mm;
        float bias = d_bsum[r];
#pragma unroll
        for (int nq = 0; nq < 2; nq++) {
            int n = n0 + tx * 8 + nq * 4;
            int t = n >> 4, b = n & 15;  // b in {0,4,8,12}: 4 batches of group b>>2
            float2 u0 = unpk(acc[mm][nq * 2 + 0]);
            float2 u1 = unpk(acc[mm][nq * 2 + 1]);
            float4 v;
            v.x = u0.x + bias;
            v.y = u0.y + bias;
            v.z = u1.x + bias;
            v.w = u1.y + bias;
            *(float4*)&d_XG[(size_t)t * (RR * Bb) + (size_t)(b >> 2) * (RR * 4) +
                            (size_t)r * 4] = v;
        }
    }
}

// ---------------- phase 2: persistent recurrent kernel -----------------------
// 4 groups x 32 CTAs. CTA (g, cl): permuted rows [64cl,64cl+64), batches
// [4g,4g+4). Warp wd owns rows [8wd,8wd+8) = hidden units {2wd, 2wd+1}.
// Lane l owns k-slice {l+32j}: h LDS fully coalesced, w read once via [k][row].
// Warp-local butterfly reduce -> each lane holds ONE gate; 4-shfl gather ->
// per-warp activations + publish. One __syncthreads per step.
__global__ __launch_bounds__(256, 1) void lstm_kernel(const float* __restrict__ c0,
                                                      float* __restrict__ out,
                                                      float* __restrict__ hT,
                                                      float* __restrict__ cT) {
    extern __shared__ float sm[];
    float* w_s = sm;                  // [512][WKS] = 136 KB
    float* h_s = w_s + Hh * WKS;      // [512][4]   = 8 KB

    const int tid = threadIdx.x;
    const int g  = blockIdx.x >> 5;
    const int cl = blockIdx.x & 31;
    const int wd = tid >> 5;          // warp 0..7
    const int l  = tid & 31;          // lane

    // lane's final ownership after reduce: bits l0,l1 = b; l2 = g1; l3 = u1; l4 = g0
    const int bb = l & 3;
    const int g1 = (l >> 2) & 1;
    const int u1 = (l >> 3) & 1;
    const int g0 = (l >> 4) & 1;
    const int rloc = 4 * u1 + 2 * g1 + g0;      // row within warp 0..7
    const bool pub = ((l & 20) == 0);           // g1==0 && g0==0 lanes (8/warp)
    const int khid  = cl * 16 + 2 * wd + u1;
    const int bglob = g * GB + bb;

    // w_s[k][row] for this CTA's 64 rows (transposed, one-time)
    for (int idx = tid; idx < Hh * 64; idx += 256) {
        int k = idx >> 6, r = idx & 63;
        w_s[k * WKS + r] = d_WhT[(size_t)k * RR + cl * 64 + r];
    }
    float c = c0[(size_t)bglob * Hh + khid];     // replicated across 4 g-lanes
    float hlast = 0.f;
    __syncthreads();

    const float4* h_s4 = (const float4*)h_s;

    for (int t = 0; t < Tt; t++) {
        // prefetch xg for this lane's final (row, batch) — warp covers 128B
        float xgv = __ldcs(&d_XG[(size_t)t * (RR * Bb) + (size_t)g * (RR * 4) +
                                 (size_t)(cl * 64 + 8 * wd + rloc) * 4 + bb]);

        // poll this thread's 64B of tagged words (k = 2*tid, 2*tid+1; all b)
        {
            const uint4* pb = (const uint4*)&d_HX[t & 1][g * 2048] + tid * 4;
            const unsigned tg = (unsigned)t;
            uint4 q0 = ldcg4(pb), q1 = ldcg4(pb + 1),
                  q2 = ldcg4(pb + 2), q3 = ldcg4(pb + 3);
            while ((q0.y != tg) | (q0.w != tg) | (q1.y != tg) | (q1.w != tg) |
                   (q2.y != tg) | (q2.w != tg) | (q3.y != tg) | (q3.w != tg)) {
                __nanosleep(32);
                q0 = ldcg4(pb); q1 = ldcg4(pb + 1);
                q2 = ldcg4(pb + 2); q3 = ldcg4(pb + 3);
            }
            ((float4*)h_s)[2 * tid] =
                make_float4(__uint_as_float(q0.x), __uint_as_float(q0.z),
                            __uint_as_float(q1.x), __uint_as_float(q1.z));
            ((float4*)h_s)[2 * tid + 1] =
                make_float4(__uint_as_float(q2.x), __uint_as_float(q2.z),
                            __uint_as_float(q3.x), __uint_as_float(q3.z));
        }
        __syncthreads();                               // h_s complete

        // FMA: lane's 16 k values x 8 rows x 4 batches.  a[rp*4+b], rp = row-pair
        unsigned long long a[16];
#pragma unroll
        for (int i = 0; i < 16; i++) a[i] = 0ull;
#pragma unroll
        for (int j = 0; j < 16; j++) {
            int k = l + 32 * j;
            ulonglong2 wA = *(const ulonglong2*)&w_s[k * WKS + 8 * wd];      // rows 0-3
            ulonglong2 wB = *(const ulonglong2*)&w_s[k * WKS + 8 * wd + 4];  // rows 4-7
            float4 hb = h_s4[k];
            unsigned long long h0 = packdup(hb.x), h1 = packdup(hb.y),
                               h2 = packdup(hb.z), h3 = packdup(hb.w);
            a[0]  = ffma2(wA.x, h0, a[0]);   a[1]  = ffma2(wA.x, h1, a[1]);
            a[2]  = ffma2(wA.x, h2, a[2]);   a[3]  = ffma2(wA.x, h3, a[3]);
            a[4]  = ffma2(wA.y, h0, a[4]);   a[5]  = ffma2(wA.y, h1, a[5]);
            a[6]  = ffma2(wA.y, h2, a[6]);   a[7]  = ffma2(wA.y, h3, a[7]);
            a[8]  = ffma2(wB.x, h0, a[8]);   a[9]  = ffma2(wB.x, h1, a[9]);
            a[10] = ffma2(wB.x, h2, a[10]);  a[11] = ffma2(wB.x, h3, a[11]);
            a[12] = ffma2(wB.y, h0, a[12]);  a[13] = ffma2(wB.y, h1, a[13]);
            a[14] = ffma2(wB.y, h2, a[14]);  a[15] = ffma2(wB.y, h3, a[15]);
        }

        // value-splitting butterfly reduce across 32 lanes.
        // Round 1 (xor 1): pin index bit0 (=b0) to l0.
        {
            int sel = l & 1;
            unsigned long long T[8];
#pragma unroll
            for (int q = 0; q < 8; q++) T[q] = a[2 * q + (sel ^ 1)];
#pragma unroll
            for (int q = 0; q < 8; q++) T[q] = shflx64(T[q], 1);
#pragma unroll
            for (int q = 0; q < 8; q++) a[q] = add2(a[2 * q + sel], T[q]);
        }
        // Round 2 (xor 2): pin b1 to l1.
        {
            int sel = (l >> 1) & 1;
            unsigned long long T[4];
#pragma unroll
            for (int q = 0; q < 4; q++) T[q] = a[2 * q + (sel ^ 1)];
#pragma unroll
            for (int q = 0; q < 4; q++) T[q] = shflx64(T[q], 2);
#pragma unroll
            for (int q = 0; q < 4; q++) a[q] = add2(a[2 * q + sel], T[q]);
        }
        // Round 3 (xor 4): pin rp bit0 (=g1) to l2.
        {
            int sel = (l >> 2) & 1;
            unsigned long long T[2];
#pragma unroll
            for (int q = 0; q < 2; q++) T[q] = a[2 * q + (sel ^ 1)];
#pragma unroll
            for (int q = 0; q < 2; q++) T[q] = shflx64(T[q], 4);
#pragma unroll
            for (int q = 0; q < 2; q++) a[q] = add2(a[2 * q + sel], T[q]);
        }
        // Round 4 (xor 8): pin rp bit1 (=u1) to l3.
        {
            int sel = (l >> 3) & 1;
            unsigned long long T = a[sel ^ 1];
            T = shflx64(T, 8);
            a[0] = add2(a[sel], T);
        }
        // Round 5 (xor 16): pin g0 to l4; result is a scalar gate.
        float gate;
        {
            float2 p = unpk(a[0]);                   // (row g0=0, row g0=1)
            float mine  = g0 ? p.y : p.x;
            float send  = g0 ? p.x : p.y;
            gate = mine + __shfl_xor_sync(0xFFFFFFFFu, send, 16);
        }
        gate += xgv;

        // gather the 4 gates of this lane's (unit, batch): vary bits l2, l4
        const int base = l & 0x0B;                    // bits 0,1,3
        float gI = __shfl_sync(0xFFFFFFFFu, gate, base);
        float gF = __shfl_sync(0xFFFFFFFFu, gate, base | 16);
        float gG = __shfl_sync(0xFFFFFFFFu, gate, base | 4);
        float gO = __shfl_sync(0xFFFFFFFFu, gate, base | 20);

        float ig = sigmoidf_(gI);
        float fg = sigmoidf_(gF);
        float gv = tanhf_(gG);
        float og = sigmoidf_(gO);
        c = fmaf(fg, c, ig * gv);
        float h = og * tanhf_(c);
        hlast = h;
        if (pub) {
            // publish: data+tag in one 8B word — no fence needed
            st_word(&d_HX[(t + 1) & 1][g * 2048 + khid * 4 + bb],
                    __float_as_uint(h), (unsigned)(t + 1));
            // background drain; nothing orders after this
            out[((size_t)bglob * Tt + t) * Hh + khid] = h;
        }
        // safe to refill h_s next iter: passing the next poll implies every
        // producer (incl. all warps of THIS CTA) finished reading h_s(t).
    }

    if (pub) {
        hT[(size_t)bglob * Hh + khid] = hlast;
        cT[(size_t)bglob * Hh + khid] = c;
    }
}

// ---------------- launch ------------------------------------------------------
extern "C" void kernel_launch(void* const* d_in, const int* in_sizes, int n_in,
                              void* d_out, int out_size) {
    const float* x  = (const float*)d_in[0];
    const float* h0 = (const float*)d_in[1];
    const float* c0 = (const float*)d_in[2];
    const float* Wi = (const float*)d_in[3];
    const float* bi = (const float*)d_in[4];
    const float* Wh = (const float*)d_in[5];
    const float* bh = (const float*)d_in[6];

    float* out = (float*)d_out;                       // [B,T,H]
    float* hT  = out + (size_t)Bb * Tt * Hh;          // [B,H]
    float* cT  = hT + (size_t)Bb * Hh;                // [B,H]

    const int lstm_smem = (Hh * WKS + Hh * GB) * 4;   // 136KB + 8KB
    cudaFuncSetAttribute(lstm_kernel, cudaFuncAttributeMaxDynamicSharedMemorySize,
                         lstm_smem);

    permute_kernel<<<RR, 128>>>(Wi, Wh, bi, bh);
    init_kernel<<<32, 256>>>(h0);
    xgemm_kernel<<<dim3((Tt * Bb) / BN, RR / BM), 256>>>(x);
    lstm_kernel<<<NG * GC, 256, lstm_smem>>>(c0, out, hT, cT);
}

// round 10
// speedup vs baseline: 1.1774x; 1.1774x over previous
#include <cuda_runtime.h>
#include <math.h>

#define Bb 16
#define Tt 2048
#define Ii 512
#define Hh 512
#define RR 2048   // 4*H, permuted row order r = 4*j + g
#define NG 4      // independent groups (each owns 4 batches)
#define GC 32     // CTAs per group
#define GB 4      // batches per group
#define ROWS 64   // permuted gate rows per CTA
#define WST 516   // w_s row stride in floats (64x516x4B = 132KB)

// ---------------- persistent device scratch (no runtime allocation) ----------
__device__ float d_WiP[RR * Ii];                 // 4 MB  permuted Wi
__device__ float d_WhP[RR * Hh];                 // 4 MB  permuted Wh
__device__ float d_bsum[RR];                     // bi+bh, permuted
__device__ float d_XG[(size_t)Tt * RR * Bb];     // 268 MB, [t][g][r][b4]
__device__ uint2 d_HX[2][NG * Hh * GB];          // tagged h words (h_bits, tag)

// ---------------- f32x2 helpers ----------------------------------------------
__device__ __forceinline__ unsigned long long ffma2(unsigned long long a,
                                                    unsigned long long b,
                                                    unsigned long long c) {
    unsigned long long d;
    asm("fma.rn.f32x2 %0, %1, %2, %3;" : "=l"(d) : "l"(a), "l"(b), "l"(c));
    return d;
}
__device__ __forceinline__ unsigned long long packdup(float x) {
    unsigned long long r;
    asm("mov.b64 %0, {%1, %1};" : "=l"(r) : "f"(x));
    return r;
}
__device__ __forceinline__ float2 unpk(unsigned long long v) {
    float2 r;
    asm("mov.b64 {%0, %1}, %2;" : "=f"(r.x), "=f"(r.y) : "l"(v));
    return r;
}

// fresh L2 read of 16B (2 tagged words), never hoisted
__device__ __forceinline__ uint4 ldcg4(const uint4* p) {
    uint4 v;
    asm volatile("ld.global.cg.v4.u32 {%0,%1,%2,%3}, [%4];"
                 : "=r"(v.x), "=r"(v.y), "=r"(v.z), "=r"(v.w)
                 : "l"(p) : "memory");
    return v;
}
// publish one tagged word (data+tag atomic in a single 8B store)
__device__ __forceinline__ void st_word(uint2* p, unsigned hbits, unsigned tag) {
    asm volatile("st.global.cg.v2.u32 [%0], {%1, %2};"
                 :: "l"(p), "r"(hbits), "r"(tag) : "memory");
}

__device__ __forceinline__ float sigmoidf_(float x) {
    return 1.f / (1.f + __expf(-x));
}
__device__ __forceinline__ float tanhf_(float x) {
    float e = __expf(2.f * x);
    return (e - 1.f) / (e + 1.f);
}

// ---------------- phase 0a: permute weights, fuse biases ---------------------
__global__ void permute_kernel(const float* __restrict__ Wi,
                               const float* __restrict__ Wh,
                               const float* __restrict__ bi,
                               const float* __restrict__ bh) {
    int rnew = blockIdx.x;            // 0..2047
    int j = rnew >> 2, g = rnew & 3;
    int rold = g * Hh + j;
    const float4* wi4 = (const float4*)(Wi + (size_t)rold * Ii);
    const float4* wh4 = (const float4*)(Wh + (size_t)rold * Hh);
    float4* wiP4 = (float4*)(d_WiP + (size_t)rnew * Ii);
    float4* whP4 = (float4*)(d_WhP + (size_t)rnew * Hh);
    for (int k = threadIdx.x; k < Ii / 4; k += blockDim.x) wiP4[k] = wi4[k];
    for (int k = threadIdx.x; k < Hh / 4; k += blockDim.x) whP4[k] = wh4[k];
    if (threadIdx.x == 0) d_bsum[rnew] = bi[rold] + bh[rold];
}

// ---------------- phase 0b: init tagged h words ------------------------------
__global__ void init_kernel(const float* __restrict__ h0) {
    int idx = blockIdx.x * blockDim.x + threadIdx.x;   // 0..8191
    if (idx < NG * Hh * GB) {
        int g = idx >> 11;
        int k = (idx & 2047) >> 2;
        int b = idx & 3;
        float h = h0[(size_t)(g * GB + b) * Hh + k];
        d_HX[0][idx] = make_uint2(__float_as_uint(h), 0u);       // tag 0 = h(0)
        d_HX[1][idx] = make_uint2(0u, 0xFFFFFFFFu);              // never matches
    }
}

// ---------------- phase 1: xg[t][g][r][b4] = WiP @ x^T + bsum ----------------
#define BM 128
#define BN 128
#define BK 16
#define LDA 132

__global__ __launch_bounds__(256, 2) void xgemm_kernel(const float* __restrict__ x) {
    __shared__ float As[BK * LDA];
    __shared__ float Bs[BK * LDA];
    const int tid = threadIdx.x;
    const int m0 = blockIdx.y * BM;
    const int n0 = blockIdx.x * BN;
    const int tx = tid & 15, ty = tid >> 4;

    unsigned long long acc[8][4];
#pragma unroll
    for (int i = 0; i < 8; i++)
#pragma unroll
        for (int j = 0; j < 4; j++) acc[i][j] = 0ull;

    for (int k0 = 0; k0 < Ii; k0 += BK) {
#pragma unroll
        for (int q = 0; q < 2; q++) {
            int slot = tid + q * 256;
            int row = slot >> 2;
            int kq4 = slot & 3;
            float4 v = *(const float4*)&d_WiP[(size_t)(m0 + row) * Ii + k0 + kq4 * 4];
            As[(kq4 * 4 + 0) * LDA + row] = v.x;
            As[(kq4 * 4 + 1) * LDA + row] = v.y;
            As[(kq4 * 4 + 2) * LDA + row] = v.z;
            As[(kq4 * 4 + 3) * LDA + row] = v.w;
        }
#pragma unroll
        for (int q = 0; q < 2; q++) {
            int slot = tid + q * 256;
            int nn = slot >> 2;
            int kq4 = slot & 3;
            int n = n0 + nn;
            int t = n >> 4, b = n & 15;
            float4 v = *(const float4*)&x[((size_t)b * Tt + t) * Ii + k0 + kq4 * 4];
            Bs[(kq4 * 4 + 0) * LDA + nn] = v.x;
            Bs[(kq4 * 4 + 1) * LDA + nn] = v.y;
            Bs[(kq4 * 4 + 2) * LDA + nn] = v.z;
            Bs[(kq4 * 4 + 3) * LDA + nn] = v.w;
        }
        __syncthreads();
#pragma unroll
        for (int kk = 0; kk < BK; kk++) {
            float a[8];
            *(float4*)&a[0] = *(const float4*)&As[kk * LDA + ty * 8];
            *(float4*)&a[4] = *(const float4*)&As[kk * LDA + ty * 8 + 4];
            ulonglong2 b01 = *(const ulonglong2*)&Bs[kk * LDA + tx * 8];
            ulonglong2 b23 = *(const ulonglong2*)&Bs[kk * LDA + tx * 8 + 4];
#pragma unroll
            for (int i = 0; i < 8; i++) {
                unsigned long long as = packdup(a[i]);
                acc[i][0] = ffma2(as, b01.x, acc[i][0]);
                acc[i][1] = ffma2(as, b01.y, acc[i][1]);
                acc[i][2] = ffma2(as, b23.x, acc[i][2]);
                acc[i][3] = ffma2(as, b23.y, acc[i][3]);
            }
        }
        __syncthreads();
    }
#pragma unroll
    for (int mm = 0; mm < 8; mm++) {
        int r = m0 + ty * 8 + mm;
        float bias = d_bsum[r];
#pragma unroll
        for (int nq = 0; nq < 2; nq++) {
            int n = n0 + tx * 8 + nq * 4;
            int t = n >> 4, b = n & 15;  // b in {0,4,8,12}: 4 batches of group b>>2
            float2 u0 = unpk(acc[mm][nq * 2 + 0]);
            float2 u1 = unpk(acc[mm][nq * 2 + 1]);
            float4 v;
            v.x = u0.x + bias;
            v.y = u0.y + bias;
            v.z = u1.x + bias;
            v.w = u1.y + bias;
            *(float4*)&d_XG[(size_t)t * (RR * Bb) + (size_t)(b >> 2) * (RR * 4) +
                            (size_t)r * 4] = v;
        }
    }
}

// ---------------- phase 2: persistent recurrent kernel -----------------------
// 4 independent groups x 32 CTAs. CTA (g, cl) owns permuted gate rows
// [64cl, 64cl+64) -> hidden [16cl, 16cl+16), batches [4g, 4g+4).
// Exchange via self-validating (h, tag) words: no flags, no fences.
__global__ __launch_bounds__(256, 1) void lstm_kernel(const float* __restrict__ c0,
                                                      float* __restrict__ out,
                                                      float* __restrict__ hT,
                                                      float* __restrict__ cT) {
    extern __shared__ float sm[];
    float* w_s  = sm;                       // 64 x 516         = 132.1 KB
    float* h_s  = w_s + ROWS * WST;         // 512 x 4 [k][b]   = 8 KB
    float* gred = h_s + Hh * GB;            // 4 x 64 x 4       = 4 KB

    const int tid = threadIdx.x;
    const int g  = blockIdx.x >> 5;
    const int cl = blockIdx.x & 31;
    const int kq = tid >> 6;       // k-split 0..3 (128 k each)
    const int rw = tid & 63;       // local gate row 0..63

    // Wh slice -> SMEM (once)
    {
        const float4* src = (const float4*)(d_WhP + (size_t)(cl * ROWS) * Hh);
        for (int i4 = tid; i4 < ROWS * Hh / 4; i4 += 256) {
            int rr = i4 >> 7;
            int k4 = i4 & 127;
            *(float4*)&w_s[rr * WST + k4 * 4] = src[i4];
        }
    }

    const int jl = tid >> 2, bb = tid & 3;          // tail mapping (tid < 64)
    const int khid  = cl * 16 + jl;
    const int bglob = g * GB + bb;
    float c = 0.f, hlast = 0.f;
    if (tid < 64) c = c0[(size_t)bglob * Hh + khid];
    __syncthreads();

    const float* wrow = w_s + rw * WST + kq * 128;
    const ulonglong2* hpp = (const ulonglong2*)h_s + kq * 128;
    float4* h_s4 = (float4*)h_s;

    for (int t = 0; t < Tt; t++) {
        // xg for this step (kq==0 threads; fully coalesced 1KB)
        float4 xgv = make_float4(0.f, 0.f, 0.f, 0.f);
        if (kq == 0)
            xgv = __ldcs((const float4*)(d_XG + (size_t)t * (RR * Bb) +
                                         (size_t)g * (RR * 4)) + (cl * ROWS + rw));

        // poll this thread's 64B of tagged words (k = 2*tid, 2*tid+1; all b).
        // Tight spin first (fast path: producer lands within ~1us), bounded
        // nanosleep backoff after that (cap poll-storm L2 pressure).
        {
            const uint4* pb = (const uint4*)&d_HX[t & 1][g * 2048] + tid * 4;
            const unsigned tg = (unsigned)t;
            int spins = 0;
            uint4 q0 = ldcg4(pb), q1 = ldcg4(pb + 1),
                  q2 = ldcg4(pb + 2), q3 = ldcg4(pb + 3);
            while ((q0.y != tg) | (q0.w != tg) | (q1.y != tg) | (q1.w != tg) |
                   (q2.y != tg) | (q2.w != tg) | (q3.y != tg) | (q3.w != tg)) {
                if (++spins > 16) __nanosleep(16);
                q0 = ldcg4(pb); q1 = ldcg4(pb + 1);
                q2 = ldcg4(pb + 2); q3 = ldcg4(pb + 3);
            }
            h_s4[2 * tid] =
                make_float4(__uint_as_float(q0.x), __uint_as_float(q0.z),
                            __uint_as_float(q1.x), __uint_as_float(q1.z));
            h_s4[2 * tid + 1] =
                make_float4(__uint_as_float(q2.x), __uint_as_float(q2.z),
                            __uint_as_float(q3.x), __uint_as_float(q3.z));
        }
        __syncthreads();                               // bar1: h_s complete

        // partial gates: row rw, 4 batches, k in [128kq, 128kq+128)
        unsigned long long a0 = 0ull, a1 = 0ull, a2 = 0ull, a3 = 0ull;
#pragma unroll 8
        for (int k4 = 0; k4 < 32; k4++) {
            float4 w4 = *(const float4*)(wrow + 4 * k4);
            ulonglong2 h0v = hpp[4 * k4 + 0];
            ulonglong2 h1v = hpp[4 * k4 + 1];
            ulonglong2 h2v = hpp[4 * k4 + 2];
            ulonglong2 h3v = hpp[4 * k4 + 3];
            unsigned long long w0 = packdup(w4.x);
            unsigned long long w1 = packdup(w4.y);
            unsigned long long w2 = packdup(w4.z);
            unsigned long long w3 = packdup(w4.w);
            a0 = ffma2(w0, h0v.x, a0);  a1 = ffma2(w0, h0v.y, a1);
            a2 = ffma2(w1, h1v.x, a2);  a3 = ffma2(w1, h1v.y, a3);
            a0 = ffma2(w2, h2v.x, a0);  a1 = ffma2(w2, h2v.y, a1);
            a2 = ffma2(w3, h3v.x, a2);  a3 = ffma2(w3, h3v.y, a3);
        }
        {
            float2 p0 = unpk(a0), p1 = unpk(a1), p2 = unpk(a2), p3 = unpk(a3);
            float4 v;
            v.x = p0.x + p2.x;
            v.y = p0.y + p2.y;
            v.z = p1.x + p3.x;
            v.w = p1.y + p3.y;
            if (kq == 0) {
                v.x += xgv.x; v.y += xgv.y; v.z += xgv.z; v.w += xgv.w;
            }
            *(float4*)&gred[(kq * 64 + rw) * 4] = v;
        }
        __syncthreads();                               // bar2: partials ready

        if (tid < 64) {
            float gate[4];
#pragma unroll
            for (int gt = 0; gt < 4; gt++) {
                int rl = 4 * jl + gt;
                gate[gt] = gred[(0 * 64 + rl) * 4 + bb] +
                           gred[(1 * 64 + rl) * 4 + bb] +
                           gred[(2 * 64 + rl) * 4 + bb] +
                           gred[(3 * 64 + rl) * 4 + bb];
            }
            float ig = sigmoidf_(gate[0]);
            float fg = sigmoidf_(gate[1]);
            float gv = tanhf_(gate[2]);
            float og = sigmoidf_(gate[3]);
            c = fmaf(fg, c, ig * gv);
            float h = og * tanhf_(c);
            hlast = h;
            // publish: data+tag in one 8B word — no fence needed
            st_word(&d_HX[(t + 1) & 1][g * 2048 + khid * 4 + bb],
                    __float_as_uint(h), (unsigned)(t + 1));
            // background drain; nothing orders after this
            out[((size_t)bglob * Tt + t) * Hh + khid] = h;
        }
        // non-tail threads proceed to next poll; gred/h_s reuse is safe:
        // a CTA only passes the next poll after ALL producers (incl. our own
        // tail) published t+1, which happens after the tail read gred(t).
    }

    if (tid < 64) {
        hT[(size_t)bglob * Hh + khid] = hlast;
        cT[(size_t)bglob * Hh + khid] = c;
    }
}

// ---------------- launch ------------------------------------------------------
extern "C" void kernel_launch(void* const* d_in, const int* in_sizes, int n_in,
                              void* d_out, int out_size) {
    const float* x  = (const float*)d_in[0];
    const float* h0 = (const float*)d_in[1];
    const float* c0 = (const float*)d_in[2];
    const float* Wi = (const float*)d_in[3];
    const float* bi = (const float*)d_in[4];
    const float* Wh = (const float*)d_in[5];
    const float* bh = (const float*)d_in[6];

    float* out = (float*)d_out;                       // [B,T,H]
    float* hT  = out + (size_t)Bb * Tt * Hh;          // [B,H]
    float* cT  = hT + (size_t)Bb * Hh;                // [B,H]

    const int lstm_smem = (ROWS * WST + Hh * GB + 4 * 64 * 4) * 4;
    cudaFuncSetAttribute(lstm_kernel, cudaFuncAttributeMaxDynamicSharedMemorySize,
                         lstm_smem);

    permute_kernel<<<RR, 128>>>(Wi, Wh, bi, bh);
    init_kernel<<<32, 256>>>(h0);
    xgemm_kernel<<<dim3((Tt * Bb) / BN, RR / BM), 256>>>(x);
    lstm_kernel<<<NG * GC, 256, lstm_smem>>>(c0, out, hT, cT);
}